// round 14
// baseline (speedup 1.0000x reference)
#include <cuda_runtime.h>
#include <cstdint>

// SoftTree: x[4096,512], gw[512,255], gb[255], pw[64,512,256], pb[64,256]
// out[b,o] = sum_l leafp[b,l] * ((x @ pw[o])[b,l] + pb[o,l])
//
// R14 vs R13:
//  1. GEMM: prefetch cp.asyncs moved AFTER compute in each unrolled stage
//     (volatile-asm order had them blocking the post-barrier tensor feed).
//  2. Prep: xt2 merged into the gates kernel (16-row blocks; x staged once
//     in smem, A-frag quads emitted from smem). One fewer launch.
// GEMM config otherwise unchanged: 2 CTAs/SM, 64x256 tile, 4 warps,
// warp tile 64x64, BK=16, 4-stage ring, 1 barrier/stage, packed operands.

#define N_BATCH   4096
#define N_IN      512
#define N_OUT     64
#define N_LEAF    256
#define N_GATE    255
#define TREE_DEPTH 8

__device__ float  d_leafp[N_BATCH * N_LEAF];                 // 4 MB
__device__ float4 d_xt2[(N_BATCH / 128) * 16 * 1024];        // 8 MB  (A quads)
__device__ float2 d_pwp[(size_t)N_OUT * 16 * 4096];          // 33.5 MB (B pairs)

__device__ __forceinline__ float rna_tf32(float f) {
    uint32_t u;
    asm("cvt.rna.tf32.f32 %0, %1;" : "=r"(u) : "f"(f));
    return __uint_as_float(u);
}
__device__ __forceinline__ uint32_t smem_u32(const void* p) {
    uint32_t a;
    asm("{ .reg .u64 t; cvta.to.shared.u64 t, %1; cvt.u32.u64 %0, t; }"
        : "=r"(a) : "l"(p));
    return a;
}

#define CP_ASYNC16(dst_u32, src_ptr) \
    asm volatile("cp.async.cg.shared.global [%0], [%1], 16;" \
                 :: "r"(dst_u32), "l"(src_ptr))
#define CP_COMMIT()  asm volatile("cp.async.commit_group;" ::: "memory")
#define CP_WAIT2()   asm volatile("cp.async.wait_group 2;" ::: "memory")

__device__ __forceinline__ void mma_tf32(float* d, const uint32_t* a,
                                         const uint32_t* b) {
    asm volatile(
        "mma.sync.aligned.m16n8k8.row.col.f32.tf32.tf32.f32 "
        "{%0,%1,%2,%3}, {%4,%5,%6,%7}, {%8,%9}, {%0,%1,%2,%3};"
        : "+f"(d[0]), "+f"(d[1]), "+f"(d[2]), "+f"(d[3])
        : "r"(a[0]), "r"(a[1]), "r"(a[2]), "r"(a[3]), "r"(b[0]), "r"(b[1]));
}

// ---------------------------------------------------------------------------
// P1: pw -> B-frag pairs (coalesced 2x float4 stores). Unchanged from R13.
//   pair (o,kt,ks,n,lr): {pw[o][kt*32+ks*8+lr][n], pw[o][...+lr+4][n]} (rna)
//   linear = ((o*16+kt)*4+ks)*1024 + n*4 + lr
// ---------------------------------------------------------------------------
__global__ __launch_bounds__(256) void pwp_kernel(const float* __restrict__ pw) {
    const int o = blockIdx.y;
    const int kt = blockIdx.x >> 2, ks = blockIdx.x & 3;
    const int n = threadIdx.x;
    const int k0 = kt * 32 + ks * 8;
    const float* src = pw + ((size_t)o * N_IN + k0) * N_LEAF + n;
    float v[8];
    #pragma unroll
    for (int j = 0; j < 8; ++j) v[j] = rna_tf32(src[j * N_LEAF]);
    float4* dst = reinterpret_cast<float4*>(
        d_pwp + ((size_t)(o * 16 + kt) * 4 + ks) * 1024 + n * 4);
    dst[0] = make_float4(v[0], v[4], v[1], v[5]);
    dst[1] = make_float4(v[2], v[6], v[3], v[7]);
}

// ---------------------------------------------------------------------------
// P0: gates + leafp + A-quad emission, 16 batch rows per block.
// Grid 256 blocks (bt = blk>>3, mb = blk&7), 256 threads.
// Dynamic smem: xs[16][XS_STRIDE] (stride 520: 16B-aligned rows, 2-way-max
// bank conflicts on quad reads) + gs[16][256].
// ---------------------------------------------------------------------------
#define XS_STRIDE 520
#define PREP_SMEM_FLOATS (16 * XS_STRIDE + 16 * 256)   // 12416 -> 49664 B

__global__ __launch_bounds__(256) void softtree_prep16_kernel(
    const float* __restrict__ x, const float* __restrict__ gw,
    const float* __restrict__ gb)
{
    extern __shared__ float psm[];
    float* xs = psm;                       // [16][XS_STRIDE]
    float* gs = psm + 16 * XS_STRIDE;      // [16][256]

    const int tid = threadIdx.x;
    const int bt  = blockIdx.x >> 3;
    const int mb  = blockIdx.x & 7;
    const int b0  = blockIdx.x * 16;

    // Phase A: stage 16 rows of x (2048 float4)
    {
        const float4* src = reinterpret_cast<const float4*>(x + (size_t)b0 * N_IN);
        #pragma unroll
        for (int it = 0; it < 8; ++it) {
            int idx = it * 256 + tid;
            int r = idx >> 7, c4 = idx & 127;
            *reinterpret_cast<float4*>(xs + r * XS_STRIDE + c4 * 4) = src[idx];
        }
    }
    __syncthreads();

    // Phase B: gates (16 rows per thread-gate)
    if (tid < N_GATE) {
        float acc[16];
        const float bias = gb[tid];
        #pragma unroll
        for (int r = 0; r < 16; ++r) acc[r] = bias;
        #pragma unroll 4
        for (int i = 0; i < N_IN; ++i) {
            float w = gw[i * N_GATE + tid];
            #pragma unroll
            for (int r = 0; r < 16; ++r)
                acc[r] = fmaf(xs[r * XS_STRIDE + i], w, acc[r]);
        }
        #pragma unroll
        for (int r = 0; r < 16; ++r)
            gs[r * 256 + tid] = 1.0f / (1.0f + expf(-acc[r]));
    }
    __syncthreads();

    // Phase C: leaf probabilities (thread = leaf)
    {
        const int l = tid;
        #pragma unroll
        for (int r = 0; r < 16; ++r) {
            float p = 1.0f;
            int index = 1;
            #pragma unroll
            for (int j = 0; j < TREE_DEPTH; ++j) {
                int bit = (l >> (TREE_DEPTH - 1 - j)) & 1;
                float g = gs[r * 256 + index - 1];
                p *= bit ? (1.0f - g) : g;
                index = 2 * index + bit;
            }
            d_leafp[(size_t)(b0 + r) * N_LEAF + l] = p;
        }
    }

    // Phase D: emit A-frag quads for this 16-row group (512 tasks of 4 quads)
    //   quad[lr] = { x[b][k], x[b+8][k], x[b][k+4], x[b+8][k+4] } rna,
    //   b = b0 + lq, k = kt*32 + ks*8 + lr
    //   dst = d_xt2[(bt*16+kt)*1024 + (mb*4+ks)*32 + lq*4 + lr]
    #pragma unroll
    for (int it = 0; it < 2; ++it) {
        int t2 = it * 256 + tid;           // 0..511
        int kt = t2 >> 5, ks = (t2 >> 3) & 3, lq = t2 & 7;
        int k0 = kt * 32 + ks * 8;
        float4 lo0 = *reinterpret_cast<const float4*>(xs + lq * XS_STRIDE + k0);
        float4 hi0 = *reinterpret_cast<const float4*>(xs + lq * XS_STRIDE + k0 + 4);
        float4 lo8 = *reinterpret_cast<const float4*>(xs + (lq + 8) * XS_STRIDE + k0);
        float4 hi8 = *reinterpret_cast<const float4*>(xs + (lq + 8) * XS_STRIDE + k0 + 4);
        float4* dst = &d_xt2[(size_t)(bt * 16 + kt) * 1024 + (mb * 4 + ks) * 32 + lq * 4];
        dst[0] = make_float4(rna_tf32(lo0.x), rna_tf32(lo8.x),
                             rna_tf32(hi0.x), rna_tf32(hi8.x));
        dst[1] = make_float4(rna_tf32(lo0.y), rna_tf32(lo8.y),
                             rna_tf32(hi0.y), rna_tf32(hi8.y));
        dst[2] = make_float4(rna_tf32(lo0.z), rna_tf32(lo8.z),
                             rna_tf32(hi0.z), rna_tf32(hi8.z));
        dst[3] = make_float4(rna_tf32(lo0.w), rna_tf32(lo8.w),
                             rna_tf32(hi0.w), rna_tf32(hi8.w));
    }
}

// ---------------------------------------------------------------------------
// GEMM: tf32 mma.sync, 2 CTAs/SM, BK=16, 4-stage ring, 1 barrier/stage,
// unrolled x4 (slot/h compile-time), COMPUTE BEFORE PREFETCH per stage.
// Grid (64 bt64, 64 o), 128 threads (4 warps, 1m x 4n), warp tile 64x64.
// ---------------------------------------------------------------------------
#define A_ST_F  1024
#define B_ST_F  4096
#define ST_F    (A_ST_F + B_ST_F)
#define N_STAGES 4
#define SMEM_FLOATS (N_STAGES * ST_F + 4 * 64)

template <int H>
__device__ __forceinline__ void load_stage_t(
    uint32_t a_base, uint32_t b_base,
    const float4* __restrict__ xa, const float2* __restrict__ bb, int tid)
{
    #pragma unroll
    for (int it = 0; it < 2; ++it) {
        int q = it * 128 + tid;                 // smem quad 0..255
        int mb = q >> 6, ks2 = (q >> 5) & 1, inner = q & 31;
        int qg = (mb * 4 + 2 * H + ks2) * 32 + inner;
        CP_ASYNC16(a_base + (uint32_t)q * 16, xa + qg);
    }
    #pragma unroll
    for (int it = 0; it < 8; ++it) {
        int i = it * 128 + tid;
        CP_ASYNC16(b_base + (uint32_t)i * 16, bb + i * 2);
    }
    CP_COMMIT();
}

__global__ __launch_bounds__(128, 2) void softtree_gemm_mma(
    const float* __restrict__ pb, float* __restrict__ out)
{
    extern __shared__ float sm[];
    float* red = sm + N_STAGES * ST_F;   // [4][64]

    const int tid  = threadIdx.x;
    const int lane = tid & 31;
    const int wn   = tid >> 5;
    const int lq   = lane >> 2;
    const int lr   = lane & 3;
    const int o    = blockIdx.y;
    const int bt64 = blockIdx.x;
    const int b0   = bt64 * 64;

    const float4* __restrict__ xa_all =
        d_xt2 + ((size_t)(bt64 >> 1) * 16) * 1024 + (bt64 & 1) * 512;
    const float2* __restrict__ bb_all = d_pwp + (size_t)o * 16 * 4096;

    const uint32_t smb = smem_u32(sm);
    const uint32_t ab0 = smb + 0 * ST_F * 4, bb0 = ab0 + A_ST_F * 4;
    const uint32_t ab1 = smb + 1 * ST_F * 4, bb1 = ab1 + A_ST_F * 4;
    const uint32_t ab2 = smb + 2 * ST_F * 4, bb2 = ab2 + A_ST_F * 4;
    const uint32_t ab3 = smb + 3 * ST_F * 4, bb3 = ab3 + A_ST_F * 4;

    float acc[4][8][4];
    #pragma unroll
    for (int mf = 0; mf < 4; ++mf)
        #pragma unroll
        for (int nf = 0; nf < 8; ++nf)
            #pragma unroll
            for (int e = 0; e < 4; ++e) acc[mf][nf][e] = 0.0f;

    auto compute_stage = [&](const float* Asb) {
        const float* Bsb = Asb + A_ST_F;
        #pragma unroll
        for (int ks2 = 0; ks2 < 2; ++ks2) {
            uint32_t af[4][4], bf[8][2];
            #pragma unroll
            for (int mf = 0; mf < 4; ++mf) {
                float4 a4 = *reinterpret_cast<const float4*>(
                    Asb + ((size_t)(mf * 64 + ks2 * 32 + lq * 4 + lr)) * 4);
                af[mf][0] = __float_as_uint(a4.x);
                af[mf][1] = __float_as_uint(a4.y);
                af[mf][2] = __float_as_uint(a4.z);
                af[mf][3] = __float_as_uint(a4.w);
            }
            #pragma unroll
            for (int nf = 0; nf < 8; ++nf) {
                const int n = wn * 64 + nf * 8 + lq;
                float2 b2 = *reinterpret_cast<const float2*>(
                    Bsb + ((size_t)(ks2 * 1024 + n * 4 + lr)) * 2);
                bf[nf][0] = __float_as_uint(b2.x);
                bf[nf][1] = __float_as_uint(b2.y);
            }
            #pragma unroll
            for (int mf = 0; mf < 4; ++mf)
                #pragma unroll
                for (int nf = 0; nf < 8; ++nf)
                    mma_tf32(acc[mf][nf], af[mf], bf[nf]);
        }
    };

    // Prologue: stages 0 (slot0,h0), 1 (slot1,h1), 2 (slot2,h0)
    load_stage_t<0>(ab0, bb0, xa_all,        bb_all,        tid);
    load_stage_t<1>(ab1, bb1, xa_all,        bb_all + 2048, tid);
    load_stage_t<0>(ab2, bb2, xa_all + 1024, bb_all + 4096, tid);

    // Main loop: 8 groups of 4 stages; compute first, then prefetch st+3.
    #pragma unroll 1
    for (int q = 0; q < 8; ++q) {
        const float4* xaq = xa_all + (size_t)(2 * q) * 1024;
        const float2* bbq = bb_all + (size_t)(4 * q) * 2048;

        // stage 4q (slot 0); prefetch 4q+3 (slot 3, h=1, kt32=2q+1)
        CP_WAIT2(); __syncthreads();
        compute_stage(sm + 0 * ST_F);
        load_stage_t<1>(ab3, bb3, xaq + 1024, bbq + 3 * 2048, tid);

        // stage 4q+1 (slot 1); prefetch 4q+4 (slot 0, h=0, kt32=2q+2)
        CP_WAIT2(); __syncthreads();
        compute_stage(sm + 1 * ST_F);
        if (q < 7)
            load_stage_t<0>(ab0, bb0, xaq + 2048, bbq + 4 * 2048, tid);

        // stage 4q+2 (slot 2); prefetch 4q+5 (slot 1, h=1, kt32=2q+2)
        CP_WAIT2(); __syncthreads();
        compute_stage(sm + 2 * ST_F);
        if (q < 7)
            load_stage_t<1>(ab1, bb1, xaq + 2048, bbq + 5 * 2048, tid);

        // stage 4q+3 (slot 3); prefetch 4q+6 (slot 2, h=0, kt32=2q+3)
        CP_WAIT2(); __syncthreads();
        compute_stage(sm + 3 * ST_F);
        if (q < 7)
            load_stage_t<0>(ab2, bb2, xaq + 3072, bbq + 6 * 2048, tid);
    }

    // Fused epilogue: s[row] = sum_n p[b,n]*(C[b,n] + pb[o,n])
    const float* __restrict__ pbo = pb + (size_t)o * N_LEAF;
    #pragma unroll
    for (int mf = 0; mf < 4; ++mf) {
        const int r0 = mf * 16 + lq;
        const int r1 = r0 + 8;
        const float* p0row = d_leafp + (size_t)(b0 + r0) * N_LEAF;
        const float* p1row = d_leafp + (size_t)(b0 + r1) * N_LEAF;
        float s0 = 0.0f, s1 = 0.0f;
        #pragma unroll
        for (int nf = 0; nf < 8; ++nf) {
            const int n = wn * 64 + nf * 8 + 2 * lr;
            float2 pbv = *reinterpret_cast<const float2*>(pbo + n);
            float2 pa  = *reinterpret_cast<const float2*>(p0row + n);
            float2 pc  = *reinterpret_cast<const float2*>(p1row + n);
            s0 = fmaf(acc[mf][nf][0] + pbv.x, pa.x, s0);
            s0 = fmaf(acc[mf][nf][1] + pbv.y, pa.y, s0);
            s1 = fmaf(acc[mf][nf][2] + pbv.x, pc.x, s1);
            s1 = fmaf(acc[mf][nf][3] + pbv.y, pc.y, s1);
        }
        s0 += __shfl_xor_sync(0xffffffffu, s0, 1);
        s0 += __shfl_xor_sync(0xffffffffu, s0, 2);
        s1 += __shfl_xor_sync(0xffffffffu, s1, 1);
        s1 += __shfl_xor_sync(0xffffffffu, s1, 2);
        if (lr == 0) {
            red[wn * 64 + r0] = s0;
            red[wn * 64 + r1] = s1;
        }
    }
    __syncthreads();

    if (tid < 64) {
        float v = red[0 * 64 + tid] + red[1 * 64 + tid] +
                  red[2 * 64 + tid] + red[3 * 64 + tid];
        out[(size_t)(b0 + tid) * N_OUT + o] = v;
    }
}

// ---------------------------------------------------------------------------
extern "C" void kernel_launch(void* const* d_in, const int* in_sizes, int n_in,
                              void* d_out, int out_size)
{
    const float* x  = (const float*)d_in[0];
    const float* gw = (const float*)d_in[1];
    const float* gb = (const float*)d_in[2];
    const float* pw = (const float*)d_in[3];
    const float* pb = (const float*)d_in[4];
    float* out = (float*)d_out;

    const int gemm_smem = SMEM_FLOATS * 4;           // 82,944 B per CTA
    cudaFuncSetAttribute(softtree_gemm_mma,
                         cudaFuncAttributeMaxDynamicSharedMemorySize, gemm_smem);
    const int prep_smem = PREP_SMEM_FLOATS * 4;      // 49,664 B
    cudaFuncSetAttribute(softtree_prep16_kernel,
                         cudaFuncAttributeMaxDynamicSharedMemorySize, prep_smem);

    pwp_kernel<<<dim3(64, 64), 256>>>(pw);
    softtree_prep16_kernel<<<N_BATCH / 16, 256, prep_smem>>>(x, gw, gb);

    dim3 grid(N_BATCH / 64, N_OUT);
    softtree_gemm_mma<<<grid, 128, gemm_smem>>>(pb, out);
}

// round 15
// speedup vs baseline: 1.0317x; 1.0317x over previous
#include <cuda_runtime.h>
#include <cstdint>

// SoftTree: x[4096,512], gw[512,255], gb[255], pw[64,512,256], pb[64,256]
// out[b,o] = sum_l leafp[b,l] * ((x @ pw[o])[b,l] + pb[o,l])
//
// R15 = bisect of R14's two confounded changes:
//   KEEP:   GEMM compute-before-prefetch per unrolled stage.
//   REVERT: prep back to R13's three separate kernels (xt2 / pwp / gates).
// GEMM config otherwise = R13: 2 CTAs/SM, 64x256 tile, 4 warps, warp tile
// 64x64, BK=16, 4-stage ring, 1 barrier/stage, unrolled x4, packed operands.

#define N_BATCH   4096
#define N_IN      512
#define N_OUT     64
#define N_LEAF    256
#define N_GATE    255
#define TREE_DEPTH 8

__device__ float  d_leafp[N_BATCH * N_LEAF];                 // 4 MB
__device__ float4 d_xt2[(N_BATCH / 128) * 16 * 1024];        // 8 MB  (A quads)
__device__ float2 d_pwp[(size_t)N_OUT * 16 * 4096];          // 33.5 MB (B pairs)

__device__ __forceinline__ float rna_tf32(float f) {
    uint32_t u;
    asm("cvt.rna.tf32.f32 %0, %1;" : "=r"(u) : "f"(f));
    return __uint_as_float(u);
}
__device__ __forceinline__ uint32_t smem_u32(const void* p) {
    uint32_t a;
    asm("{ .reg .u64 t; cvta.to.shared.u64 t, %1; cvt.u32.u64 %0, t; }"
        : "=r"(a) : "l"(p));
    return a;
}

#define CP_ASYNC16(dst_u32, src_ptr) \
    asm volatile("cp.async.cg.shared.global [%0], [%1], 16;" \
                 :: "r"(dst_u32), "l"(src_ptr))
#define CP_COMMIT()  asm volatile("cp.async.commit_group;" ::: "memory")
#define CP_WAIT2()   asm volatile("cp.async.wait_group 2;" ::: "memory")

__device__ __forceinline__ void mma_tf32(float* d, const uint32_t* a,
                                         const uint32_t* b) {
    asm volatile(
        "mma.sync.aligned.m16n8k8.row.col.f32.tf32.tf32.f32 "
        "{%0,%1,%2,%3}, {%4,%5,%6,%7}, {%8,%9}, {%0,%1,%2,%3};"
        : "+f"(d[0]), "+f"(d[1]), "+f"(d[2]), "+f"(d[3])
        : "r"(a[0]), "r"(a[1]), "r"(a[2]), "r"(a[3]), "r"(b[0]), "r"(b[1]));
}

// ---------------------------------------------------------------------------
// P0: x -> A-frag quads (R13 version).
//   quad (bt,kt,mb,ks,lq,lr): rows b=bt*128+mb*16+lq(+8),
//   cols k=kt*32+ks*8+lr(+4); linear=(bt*16+kt)*1024+(mb*4+ks)*32+lq*4+lr
// ---------------------------------------------------------------------------
__global__ __launch_bounds__(256) void xt2_kernel(const float* __restrict__ x) {
    const int kt = blockIdx.x, bt = blockIdx.y;
    #pragma unroll
    for (int it = 0; it < 4; ++it) {
        int qid = it * 256 + threadIdx.x;
        int mb = qid >> 7, ks = (qid >> 5) & 3, lq = (qid >> 2) & 7, lr = qid & 3;
        int b = bt * 128 + mb * 16 + lq;
        int k = kt * 32 + ks * 8 + lr;
        const float* xb = x + (size_t)b * N_IN + k;
        float4 q;
        q.x = rna_tf32(xb[0]);
        q.y = rna_tf32(xb[8 * N_IN]);
        q.z = rna_tf32(xb[4]);
        q.w = rna_tf32(xb[8 * N_IN + 4]);
        d_xt2[(size_t)(bt * 16 + kt) * 1024 + qid] = q;
    }
}

// ---------------------------------------------------------------------------
// P1: pw -> B-frag pairs (coalesced 2x float4 stores). Unchanged.
// ---------------------------------------------------------------------------
__global__ __launch_bounds__(256) void pwp_kernel(const float* __restrict__ pw) {
    const int o = blockIdx.y;
    const int kt = blockIdx.x >> 2, ks = blockIdx.x & 3;
    const int n = threadIdx.x;
    const int k0 = kt * 32 + ks * 8;
    const float* src = pw + ((size_t)o * N_IN + k0) * N_LEAF + n;
    float v[8];
    #pragma unroll
    for (int j = 0; j < 8; ++j) v[j] = rna_tf32(src[j * N_LEAF]);
    float4* dst = reinterpret_cast<float4*>(
        d_pwp + ((size_t)(o * 16 + kt) * 4 + ks) * 1024 + n * 4);
    dst[0] = make_float4(v[0], v[4], v[1], v[5]);
    dst[1] = make_float4(v[2], v[6], v[3], v[7]);
}

// ---------------------------------------------------------------------------
// K2: gates + leaf probabilities (R13 version, 8 rows/block)
// ---------------------------------------------------------------------------
#define K1_ROWS 8
__global__ __launch_bounds__(256) void softtree_gates_kernel(
    const float* __restrict__ x, const float* __restrict__ gw,
    const float* __restrict__ gb)
{
    __shared__ float xs[K1_ROWS][N_IN];
    __shared__ float gs[K1_ROWS][N_LEAF];
    const int tid = threadIdx.x;
    const int b0  = blockIdx.x * K1_ROWS;

    {
        const float4* src = reinterpret_cast<const float4*>(x + (size_t)b0 * N_IN);
        float4* dst = reinterpret_cast<float4*>(&xs[0][0]);
        #pragma unroll
        for (int it = 0; it < (K1_ROWS * N_IN / 4) / 256; ++it)
            dst[it * 256 + tid] = src[it * 256 + tid];
    }
    __syncthreads();

    if (tid < N_GATE) {
        float acc[K1_ROWS];
        const float bias = gb[tid];
        #pragma unroll
        for (int r = 0; r < K1_ROWS; ++r) acc[r] = bias;
        #pragma unroll 4
        for (int i = 0; i < N_IN; ++i) {
            float w = gw[i * N_GATE + tid];
            #pragma unroll
            for (int r = 0; r < K1_ROWS; ++r)
                acc[r] = fmaf(xs[r][i], w, acc[r]);
        }
        #pragma unroll
        for (int r = 0; r < K1_ROWS; ++r)
            gs[r][tid] = 1.0f / (1.0f + expf(-acc[r]));
    }
    __syncthreads();

    const int l = tid;
    #pragma unroll
    for (int r = 0; r < K1_ROWS; ++r) {
        float p = 1.0f;
        int index = 1;
        #pragma unroll
        for (int j = 0; j < TREE_DEPTH; ++j) {
            int bit = (l >> (TREE_DEPTH - 1 - j)) & 1;
            float g = gs[r][index - 1];
            p *= bit ? (1.0f - g) : g;
            index = 2 * index + bit;
        }
        d_leafp[(size_t)(b0 + r) * N_LEAF + l] = p;
    }
}

// ---------------------------------------------------------------------------
// GEMM: tf32 mma.sync, 2 CTAs/SM, BK=16, 4-stage ring, 1 barrier/stage,
// unrolled x4 (slot/h compile-time), COMPUTE BEFORE PREFETCH per stage.
// Grid (64 bt64, 64 o), 128 threads (4 warps, 1m x 4n), warp tile 64x64.
// ---------------------------------------------------------------------------
#define A_ST_F  1024
#define B_ST_F  4096
#define ST_F    (A_ST_F + B_ST_F)
#define N_STAGES 4
#define SMEM_FLOATS (N_STAGES * ST_F + 4 * 64)

template <int H>
__device__ __forceinline__ void load_stage_t(
    uint32_t a_base, uint32_t b_base,
    const float4* __restrict__ xa, const float2* __restrict__ bb, int tid)
{
    #pragma unroll
    for (int it = 0; it < 2; ++it) {
        int q = it * 128 + tid;                 // smem quad 0..255
        int mb = q >> 6, ks2 = (q >> 5) & 1, inner = q & 31;
        int qg = (mb * 4 + 2 * H + ks2) * 32 + inner;
        CP_ASYNC16(a_base + (uint32_t)q * 16, xa + qg);
    }
    #pragma unroll
    for (int it = 0; it < 8; ++it) {
        int i = it * 128 + tid;
        CP_ASYNC16(b_base + (uint32_t)i * 16, bb + i * 2);
    }
    CP_COMMIT();
}

__global__ __launch_bounds__(128, 2) void softtree_gemm_mma(
    const float* __restrict__ pb, float* __restrict__ out)
{
    extern __shared__ float sm[];
    float* red = sm + N_STAGES * ST_F;   // [4][64]

    const int tid  = threadIdx.x;
    const int lane = tid & 31;
    const int wn   = tid >> 5;
    const int lq   = lane >> 2;
    const int lr   = lane & 3;
    const int o    = blockIdx.y;
    const int bt64 = blockIdx.x;
    const int b0   = bt64 * 64;

    const float4* __restrict__ xa_all =
        d_xt2 + ((size_t)(bt64 >> 1) * 16) * 1024 + (bt64 & 1) * 512;
    const float2* __restrict__ bb_all = d_pwp + (size_t)o * 16 * 4096;

    const uint32_t smb = smem_u32(sm);
    const uint32_t ab0 = smb + 0 * ST_F * 4, bb0 = ab0 + A_ST_F * 4;
    const uint32_t ab1 = smb + 1 * ST_F * 4, bb1 = ab1 + A_ST_F * 4;
    const uint32_t ab2 = smb + 2 * ST_F * 4, bb2 = ab2 + A_ST_F * 4;
    const uint32_t ab3 = smb + 3 * ST_F * 4, bb3 = ab3 + A_ST_F * 4;

    float acc[4][8][4];
    #pragma unroll
    for (int mf = 0; mf < 4; ++mf)
        #pragma unroll
        for (int nf = 0; nf < 8; ++nf)
            #pragma unroll
            for (int e = 0; e < 4; ++e) acc[mf][nf][e] = 0.0f;

    auto compute_stage = [&](const float* Asb) {
        const float* Bsb = Asb + A_ST_F;
        #pragma unroll
        for (int ks2 = 0; ks2 < 2; ++ks2) {
            uint32_t af[4][4], bf[8][2];
            #pragma unroll
            for (int mf = 0; mf < 4; ++mf) {
                float4 a4 = *reinterpret_cast<const float4*>(
                    Asb + ((size_t)(mf * 64 + ks2 * 32 + lq * 4 + lr)) * 4);
                af[mf][0] = __float_as_uint(a4.x);
                af[mf][1] = __float_as_uint(a4.y);
                af[mf][2] = __float_as_uint(a4.z);
                af[mf][3] = __float_as_uint(a4.w);
            }
            #pragma unroll
            for (int nf = 0; nf < 8; ++nf) {
                const int n = wn * 64 + nf * 8 + lq;
                float2 b2 = *reinterpret_cast<const float2*>(
                    Bsb + ((size_t)(ks2 * 1024 + n * 4 + lr)) * 2);
                bf[nf][0] = __float_as_uint(b2.x);
                bf[nf][1] = __float_as_uint(b2.y);
            }
            #pragma unroll
            for (int mf = 0; mf < 4; ++mf)
                #pragma unroll
                for (int nf = 0; nf < 8; ++nf)
                    mma_tf32(acc[mf][nf], af[mf], bf[nf]);
        }
    };

    // Prologue: stages 0 (slot0,h0), 1 (slot1,h1), 2 (slot2,h0)
    load_stage_t<0>(ab0, bb0, xa_all,        bb_all,        tid);
    load_stage_t<1>(ab1, bb1, xa_all,        bb_all + 2048, tid);
    load_stage_t<0>(ab2, bb2, xa_all + 1024, bb_all + 4096, tid);

    // Main loop: 8 groups of 4 stages; compute first, then prefetch st+3.
    #pragma unroll 1
    for (int q = 0; q < 8; ++q) {
        const float4* xaq = xa_all + (size_t)(2 * q) * 1024;
        const float2* bbq = bb_all + (size_t)(4 * q) * 2048;

        // stage 4q (slot 0); prefetch 4q+3 (slot 3, h=1, kt32=2q+1)
        CP_WAIT2(); __syncthreads();
        compute_stage(sm + 0 * ST_F);
        load_stage_t<1>(ab3, bb3, xaq + 1024, bbq + 3 * 2048, tid);

        // stage 4q+1 (slot 1); prefetch 4q+4 (slot 0, h=0, kt32=2q+2)
        CP_WAIT2(); __syncthreads();
        compute_stage(sm + 1 * ST_F);
        if (q < 7)
            load_stage_t<0>(ab0, bb0, xaq + 2048, bbq + 4 * 2048, tid);

        // stage 4q+2 (slot 2); prefetch 4q+5 (slot 1, h=1, kt32=2q+2)
        CP_WAIT2(); __syncthreads();
        compute_stage(sm + 2 * ST_F);
        if (q < 7)
            load_stage_t<1>(ab1, bb1, xaq + 2048, bbq + 5 * 2048, tid);

        // stage 4q+3 (slot 3); prefetch 4q+6 (slot 2, h=0, kt32=2q+3)
        CP_WAIT2(); __syncthreads();
        compute_stage(sm + 3 * ST_F);
        if (q < 7)
            load_stage_t<0>(ab2, bb2, xaq + 3072, bbq + 6 * 2048, tid);
    }

    // Fused epilogue: s[row] = sum_n p[b,n]*(C[b,n] + pb[o,n])
    const float* __restrict__ pbo = pb + (size_t)o * N_LEAF;
    #pragma unroll
    for (int mf = 0; mf < 4; ++mf) {
        const int r0 = mf * 16 + lq;
        const int r1 = r0 + 8;
        const float* p0row = d_leafp + (size_t)(b0 + r0) * N_LEAF;
        const float* p1row = d_leafp + (size_t)(b0 + r1) * N_LEAF;
        float s0 = 0.0f, s1 = 0.0f;
        #pragma unroll
        for (int nf = 0; nf < 8; ++nf) {
            const int n = wn * 64 + nf * 8 + 2 * lr;
            float2 pbv = *reinterpret_cast<const float2*>(pbo + n);
            float2 pa  = *reinterpret_cast<const float2*>(p0row + n);
            float2 pc  = *reinterpret_cast<const float2*>(p1row + n);
            s0 = fmaf(acc[mf][nf][0] + pbv.x, pa.x, s0);
            s0 = fmaf(acc[mf][nf][1] + pbv.y, pa.y, s0);
            s1 = fmaf(acc[mf][nf][2] + pbv.x, pc.x, s1);
            s1 = fmaf(acc[mf][nf][3] + pbv.y, pc.y, s1);
        }
        s0 += __shfl_xor_sync(0xffffffffu, s0, 1);
        s0 += __shfl_xor_sync(0xffffffffu, s0, 2);
        s1 += __shfl_xor_sync(0xffffffffu, s1, 1);
        s1 += __shfl_xor_sync(0xffffffffu, s1, 2);
        if (lr == 0) {
            red[wn * 64 + r0] = s0;
            red[wn * 64 + r1] = s1;
        }
    }
    __syncthreads();

    if (tid < 64) {
        float v = red[0 * 64 + tid] + red[1 * 64 + tid] +
                  red[2 * 64 + tid] + red[3 * 64 + tid];
        out[(size_t)(b0 + tid) * N_OUT + o] = v;
    }
}

// ---------------------------------------------------------------------------
extern "C" void kernel_launch(void* const* d_in, const int* in_sizes, int n_in,
                              void* d_out, int out_size)
{
    const float* x  = (const float*)d_in[0];
    const float* gw = (const float*)d_in[1];
    const float* gb = (const float*)d_in[2];
    const float* pw = (const float*)d_in[3];
    const float* pb = (const float*)d_in[4];
    float* out = (float*)d_out;

    const int smem_bytes = SMEM_FLOATS * 4;     // 82,944 B per CTA
    cudaFuncSetAttribute(softtree_gemm_mma,
                         cudaFuncAttributeMaxDynamicSharedMemorySize, smem_bytes);

    xt2_kernel<<<dim3(16, 32), 256>>>(x);
    pwp_kernel<<<dim3(64, 64), 256>>>(pw);
    softtree_gates_kernel<<<N_BATCH / K1_ROWS, 256>>>(x, gw, gb);

    dim3 grid(N_BATCH / 64, N_OUT);
    softtree_gemm_mma<<<grid, 128, smem_bytes>>>(pb, out);
}